// round 7
// baseline (speedup 1.0000x reference)
#include <cuda_runtime.h>
#include <math.h>

// ---------------------------------------------------------------------------
// MixedDecoder: gated mixture-of-experts MLP decoder.
//   B=32, T=512, LATENT=64, COND=448, HIDDEN=1024, OUT=512, E=8
// Pipeline: gate MLP+softmax -> per-layer (weight mix, batched GEMM+bias+leaky)
// ---------------------------------------------------------------------------

#define NB 32
#define NT 512
#define NE 8

#define LRELU(v) ((v) > 0.0f ? (v) : 0.01f * (v))

// Scratch (device globals per harness rules; zero-init -> .bss, no file bloat)
__device__ __align__(16) float g_coef[(size_t)NB * NT * NE];          // 0.5 MB
__device__ __align__(16) float g_wm[(size_t)NB * 1536 * 1024];        // 201 MB
__device__ __align__(16) float g_act0[(size_t)NB * NT * 1024];        // 67 MB
__device__ __align__(16) float g_act1[(size_t)NB * NT * 1024];        // 67 MB

// ---------------------------------------------------------------------------
// Gate: per token, h1=leaky(x@gw0+gb0) [64], h2=leaky(h1@gw1+gb1) [64],
//       coef = softmax(h2@gw2+gb2) [8].  One block (64 threads) per token.
// ---------------------------------------------------------------------------
__global__ void gate_kernel(const float* __restrict__ z, const float* __restrict__ c,
                            const float* __restrict__ gw0, const float* __restrict__ gb0,
                            const float* __restrict__ gw1, const float* __restrict__ gb1,
                            const float* __restrict__ gw2, const float* __restrict__ gb2)
{
    __shared__ float xs[512];
    __shared__ float hs[64];
    __shared__ float ls[NE];
    const int token = blockIdx.x;           // b*512 + t
    const int tid = threadIdx.x;            // 0..63

    const float* zr = z + (size_t)token * 64;
    const float* cr = c + (size_t)token * 448;
    xs[tid] = zr[tid];
#pragma unroll
    for (int j = 0; j < 7; j++) xs[64 + j * 64 + tid] = cr[j * 64 + tid];
    __syncthreads();

    float h = gb0[tid];
#pragma unroll 8
    for (int k = 0; k < 512; k++) h = fmaf(xs[k], gw0[k * 64 + tid], h);
    h = LRELU(h);
    hs[tid] = h;
    __syncthreads();

    float h2 = gb1[tid];
#pragma unroll
    for (int k = 0; k < 64; k++) h2 = fmaf(hs[k], gw1[k * 64 + tid], h2);
    h2 = LRELU(h2);
    __syncthreads();          // everyone done reading hs
    hs[tid] = h2;
    __syncthreads();

    if (tid < NE) {
        float l = gb2[tid];
#pragma unroll
        for (int k = 0; k < 64; k++) l = fmaf(hs[k], gw2[k * NE + tid], l);
        ls[tid] = l;
    }
    __syncthreads();
    if (tid == 0) {
        float mx = ls[0];
#pragma unroll
        for (int e = 1; e < NE; e++) mx = fmaxf(mx, ls[e]);
        float ex[NE], s = 0.0f;
#pragma unroll
        for (int e = 0; e < NE; e++) { ex[e] = expf(ls[e] - mx); s += ex[e]; }
        const float inv = 1.0f / s;
#pragma unroll
        for (int e = 0; e < NE; e++) g_coef[(size_t)token * NE + e] = ex[e] * inv;
    }
}

// ---------------------------------------------------------------------------
// Weight mix: wm[b] = sum_e coef0[b,e] * w[e].  Each thread owns one float4
// of the (fin*fout) weight plane, loads all 8 experts once, writes 32 batches.
// Reads w once (193MB total), writes wm (772MB total) -> HBM bound ~130us.
// ---------------------------------------------------------------------------
__global__ void mix_kernel(const float* __restrict__ w, int nPerExpert)
{
    __shared__ float c0[NB * NE];
    const int tid = threadIdx.x;            // 256 threads
    // coef0[b][e] = coef at token (b*512 + 0)
    c0[tid] = g_coef[(size_t)(tid >> 3) * NT * NE + (tid & 7)];
    __syncthreads();

    const int n4 = nPerExpert >> 2;
    const int idx4 = blockIdx.x * 256 + tid;
    if (idx4 >= n4) return;

    float4 wv[NE];
#pragma unroll
    for (int e = 0; e < NE; e++)
        wv[e] = ((const float4*)w)[(size_t)e * n4 + idx4];

    for (int b = 0; b < NB; b++) {
        float4 a = make_float4(0.f, 0.f, 0.f, 0.f);
#pragma unroll
        for (int e = 0; e < NE; e++) {
            const float s = c0[b * NE + e];
            a.x = fmaf(s, wv[e].x, a.x);
            a.y = fmaf(s, wv[e].y, a.y);
            a.z = fmaf(s, wv[e].z, a.z);
            a.w = fmaf(s, wv[e].w, a.w);
        }
        ((float4*)g_wm)[(size_t)b * n4 + idx4] = a;
    }
}

// ---------------------------------------------------------------------------
// Batched GEMM with virtual concat input + fused per-token bias mix + leaky.
//   C[b](512 x fout) = A[b](512 x fin) @ wm[b](fin x fout) + bm, bm from coef.
// BM=128, BN=128, BK=16, 256 threads, 8x8 per-thread tile, packed fma.f32x2.
// ---------------------------------------------------------------------------
#define BM 128
#define BN 128
#define BK 16

__global__ __launch_bounds__(256, 2)
void gemm_kernel(const float* __restrict__ z, const float* __restrict__ c,
                 const float* __restrict__ bias, float* __restrict__ dout,
                 int prevSel, int outSel, int fin, int fout, int doAct)
{
    __shared__ float As[BK][BM + 4];   // +4 pad keeps 16B row alignment
    __shared__ float Bs[BK][BN];

    const int b  = blockIdx.z;
    const int n0 = blockIdx.x * BN;
    const int m0 = blockIdx.y * BM;
    const int tid = threadIdx.x;

    const float* prev = (prevSel < 0) ? (const float*)0
                        : (prevSel == 0 ? g_act0 : g_act1);
    float* outp = (outSel == 0) ? g_act0 : (outSel == 1 ? g_act1 : dout);
    const float* wmb = g_wm + (size_t)b * fin * fout;

    const int tm = (tid >> 4) * 8;     // 0..120
    const int tn = (tid & 15) * 8;     // 0..120

    unsigned long long acc[8][4];      // 8 rows x 4 f32x2 pairs (8 cols)
#pragma unroll
    for (int i = 0; i < 8; i++)
#pragma unroll
        for (int j = 0; j < 4; j++) acc[i][j] = 0ULL;

    for (int k0 = 0; k0 < fin; k0 += BK) {
        // ----- select concat segment for this K tile (boundaries 64, 512) ---
        const float* aseg; int astride, acol;
        if (k0 < 64)                    { aseg = z    + (size_t)b * NT * 64;   astride = 64;   acol = k0; }
        else if (!prev || k0 < 512)     { aseg = c    + (size_t)b * NT * 448;  astride = 448;  acol = k0 - 64; }
        else                            { aseg = prev + (size_t)b * NT * 1024; astride = 1024; acol = k0 - 512; }

        // ----- load A tile (128 x 16), transposed into As[k][m] -------------
#pragma unroll
        for (int j = 0; j < 2; j++) {
            const int idx = tid + j * 256;
            const int r  = idx >> 2;
            const int qc = (idx & 3) << 2;
            const float4 v = *(const float4*)(aseg + (size_t)(m0 + r) * astride + acol + qc);
            As[qc + 0][r] = v.x; As[qc + 1][r] = v.y;
            As[qc + 2][r] = v.z; As[qc + 3][r] = v.w;
        }
        // ----- load B tile (16 x 128) ---------------------------------------
#pragma unroll
        for (int j = 0; j < 2; j++) {
            const int idx = tid + j * 256;
            const int kr = idx >> 5;
            const int qn = (idx & 31) << 2;
            *(float4*)(&Bs[kr][qn]) =
                *(const float4*)(wmb + (size_t)(k0 + kr) * fout + n0 + qn);
        }
        __syncthreads();

        // ----- mainloop: packed f32x2 FMAs ----------------------------------
#pragma unroll
        for (int k = 0; k < BK; k++) {
            float av[8];
            *(float4*)&av[0] = *(const float4*)&As[k][tm];
            *(float4*)&av[4] = *(const float4*)&As[k][tm + 4];
            const ulonglong2 b01 = *(const ulonglong2*)&Bs[k][tn];
            const ulonglong2 b23 = *(const ulonglong2*)&Bs[k][tn + 4];
            unsigned long long bv[4];
            bv[0] = b01.x; bv[1] = b01.y; bv[2] = b23.x; bv[3] = b23.y;
#pragma unroll
            for (int i = 0; i < 8; i++) {
                unsigned long long ap;
                asm("mov.b64 %0, {%1, %1};" : "=l"(ap) : "f"(av[i]));
#pragma unroll
                for (int j = 0; j < 4; j++)
                    asm("fma.rn.f32x2 %0, %1, %2, %0;"
                        : "+l"(acc[i][j]) : "l"(ap), "l"(bv[j]));
            }
        }
        __syncthreads();
    }

    // ----- epilogue: bm[t][o] = sum_e coef[b,t,e]*bias[e,o], then leaky -----
    // Reuse Bs rows 0..7 for the bias tile and As (flat) for 128x8 coef rows.
    float* cf = &As[0][0];
#pragma unroll
    for (int j = 0; j < 4; j++) {
        const int idx = tid + j * 256;                 // 0..1023
        const int e  = idx >> 7;
        const int nn = idx & 127;
        Bs[e][nn] = bias[(size_t)e * fout + n0 + nn];
        cf[idx]   = g_coef[((size_t)b * NT + m0) * NE + idx];
    }
    __syncthreads();

#pragma unroll
    for (int i = 0; i < 8; i++) {
        float vout[8];
#pragma unroll
        for (int j = 0; j < 4; j++) {
            float lo, hi;
            asm("mov.b64 {%0, %1}, %2;" : "=f"(lo), "=f"(hi) : "l"(acc[i][j]));
            vout[2 * j] = lo; vout[2 * j + 1] = hi;
        }
        const float* cfr = &cf[(tm + i) * NE];
#pragma unroll
        for (int j = 0; j < 8; j++) {
            float bm = 0.0f;
#pragma unroll
            for (int e = 0; e < NE; e++) bm = fmaf(cfr[e], Bs[e][tn + j], bm);
            float v = vout[j] + bm;
            if (doAct) v = LRELU(v);
            vout[j] = v;
        }
        float* orow = outp + ((size_t)b * NT + m0 + tm + i) * fout + n0 + tn;
        *(float4*)orow       = *(float4*)&vout[0];
        *(float4*)(orow + 4) = *(float4*)&vout[4];
    }
}

// ---------------------------------------------------------------------------
extern "C" void kernel_launch(void* const* d_in, const int* in_sizes, int n_in,
                              void* d_out, int out_size)
{
    (void)in_sizes; (void)n_in; (void)out_size;
    const float* z  = (const float*)d_in[0];
    const float* c  = (const float*)d_in[1];
    const float* w[5]  = { (const float*)d_in[2], (const float*)d_in[4],
                           (const float*)d_in[6], (const float*)d_in[8],
                           (const float*)d_in[10] };
    const float* bs[5] = { (const float*)d_in[3], (const float*)d_in[5],
                           (const float*)d_in[7], (const float*)d_in[9],
                           (const float*)d_in[11] };
    const float* gw0 = (const float*)d_in[12];
    const float* gb0 = (const float*)d_in[13];
    const float* gw1 = (const float*)d_in[14];
    const float* gb1 = (const float*)d_in[15];
    const float* gw2 = (const float*)d_in[16];
    const float* gb2 = (const float*)d_in[17];
    float* out = (float*)d_out;

    gate_kernel<<<NB * NT, 64>>>(z, c, gw0, gb0, gw1, gb1, gw2, gb2);

    static const int fins[5]    = { 512, 1536, 1536, 1536, 1536 };
    static const int fouts[5]   = { 1024, 1024, 1024, 1024, 512 };
    static const int prevSel[5] = { -1, 0, 1, 0, 1 };
    static const int outSel[5]  = { 0, 1, 0, 1, 2 };

    for (int L = 0; L < 5; L++) {
        const int n = fins[L] * fouts[L];
        mix_kernel<<<(n / 4 + 255) / 256, 256>>>(w[L], n);
        dim3 grid(fouts[L] / BN, NT / BM, NB);
        gemm_kernel<<<grid, 256>>>(z, c, bs[L], out,
                                   prevSel[L], outSel[L],
                                   fins[L], fouts[L], (L < 4) ? 1 : 0);
    }
}

// round 14
// speedup vs baseline: 2.0874x; 2.0874x over previous
#include <cuda_runtime.h>
#include <cuda_bf16.h>
#include <math.h>
#include <stdint.h>

// ===========================================================================
// MixedDecoder on GB300 (compute_103 PTX target -> no tcgen05; use legacy
// tensor-core path: ldmatrix + mma.sync.m16n8k16 bf16, 3-pass fp32 split).
//   B=32, T=512, LATENT=64, COND=448, HIDDEN=1024, OUT=512, E=8
//   D = Ahi@Bhi + Ahi@Blo + Alo@Bhi   (each operand bf16, accum fp32)
// ===========================================================================

#define NB 32
#define NT 512
#define NE 8
#define KMAX 1536
#define LRELU(v) ((v) > 0.0f ? (v) : 0.01f * (v))

// ---------------- device scratch (allocation-free rule) --------------------
__device__ __align__(16) float         g_coef[(size_t)NB * NT * NE];
__device__ __align__(16) __nv_bfloat16 g_whi [(size_t)NB * 1536 * 1024]; // [b][n][k]
__device__ __align__(16) __nv_bfloat16 g_wlo [(size_t)NB * 1536 * 1024];
// ping-pong full input buffers [b][t][1536] = [z(64) | c(448) | act(1024)]
__device__ __align__(16) __nv_bfloat16 g_A0hi[(size_t)NB * NT * KMAX];
__device__ __align__(16) __nv_bfloat16 g_A0lo[(size_t)NB * NT * KMAX];
__device__ __align__(16) __nv_bfloat16 g_A1hi[(size_t)NB * NT * KMAX];
__device__ __align__(16) __nv_bfloat16 g_A1lo[(size_t)NB * NT * KMAX];

// ---------------- helpers --------------------------------------------------
__device__ __forceinline__ uint32_t smem_to_u32(const void* p) {
    uint32_t a;
    asm("{ .reg .u64 t; cvta.to.shared.u64 t, %1; cvt.u32.u64 %0, t; }" : "=r"(a) : "l"(p));
    return a;
}
#define SWZ128(off) ((off) ^ (((off) >> 3) & 0x70))

__device__ __forceinline__ void cp16(uint32_t dst, const void* src) {
    asm volatile("cp.async.cg.shared.global [%0], [%1], 16;" :: "r"(dst), "l"(src));
}
__device__ __forceinline__ void cp_commit() {
    asm volatile("cp.async.commit_group;" ::: "memory");
}

__device__ __forceinline__ void ldsm4(uint32_t* r, uint32_t addr) {
    asm volatile("ldmatrix.sync.aligned.m8n8.x4.shared.b16 {%0,%1,%2,%3}, [%4];"
                 : "=r"(r[0]), "=r"(r[1]), "=r"(r[2]), "=r"(r[3]) : "r"(addr));
}
__device__ __forceinline__ void mma16816(float* d, const uint32_t* a, const uint32_t* b) {
    asm volatile(
        "mma.sync.aligned.m16n8k16.row.col.f32.bf16.bf16.f32 "
        "{%0,%1,%2,%3}, {%4,%5,%6,%7}, {%8,%9}, {%0,%1,%2,%3};"
        : "+f"(d[0]), "+f"(d[1]), "+f"(d[2]), "+f"(d[3])
        : "r"(a[0]), "r"(a[1]), "r"(a[2]), "r"(a[3]), "r"(b[0]), "r"(b[1]));
}

// split 8 fp32 -> packed bf16 hi (uint4) + bf16 lo (uint4), memory order
__device__ __forceinline__ void split8(const float* v, uint4& hv, uint4& lv) {
    uint32_t hs[8], ls[8];
#pragma unroll
    for (int i = 0; i < 8; i++) {
        __nv_bfloat16 h = __float2bfloat16(v[i]);
        float lo = v[i] - __bfloat162float(h);
        __nv_bfloat16 l = __float2bfloat16(lo);
        hs[i] = (uint32_t)__bfloat16_as_ushort(h);
        ls[i] = (uint32_t)__bfloat16_as_ushort(l);
    }
    hv.x = hs[0] | (hs[1] << 16); hv.y = hs[2] | (hs[3] << 16);
    hv.z = hs[4] | (hs[5] << 16); hv.w = hs[6] | (hs[7] << 16);
    lv.x = ls[0] | (ls[1] << 16); lv.y = ls[2] | (ls[3] << 16);
    lv.z = ls[4] | (ls[5] << 16); lv.w = ls[6] | (ls[7] << 16);
}

// ---------------------------------------------------------------------------
// Gate MLP + softmax -> g_coef
// ---------------------------------------------------------------------------
__global__ void gate_kernel(const float* __restrict__ z, const float* __restrict__ c,
                            const float* __restrict__ gw0, const float* __restrict__ gb0,
                            const float* __restrict__ gw1, const float* __restrict__ gb1,
                            const float* __restrict__ gw2, const float* __restrict__ gb2)
{
    __shared__ float xs[512];
    __shared__ float hs[64];
    __shared__ float ls[NE];
    const int token = blockIdx.x;
    const int tid = threadIdx.x;

    const float* zr = z + (size_t)token * 64;
    const float* cr = c + (size_t)token * 448;
    xs[tid] = zr[tid];
#pragma unroll
    for (int j = 0; j < 7; j++) xs[64 + j * 64 + tid] = cr[j * 64 + tid];
    __syncthreads();

    float h = gb0[tid];
#pragma unroll 8
    for (int k = 0; k < 512; k++) h = fmaf(xs[k], gw0[k * 64 + tid], h);
    h = LRELU(h);
    hs[tid] = h;
    __syncthreads();

    float h2 = gb1[tid];
#pragma unroll
    for (int k = 0; k < 64; k++) h2 = fmaf(hs[k], gw1[k * 64 + tid], h2);
    h2 = LRELU(h2);
    __syncthreads();
    hs[tid] = h2;
    __syncthreads();

    if (tid < NE) {
        float l = gb2[tid];
#pragma unroll
        for (int k = 0; k < 64; k++) l = fmaf(hs[k], gw2[k * NE + tid], l);
        ls[tid] = l;
    }
    __syncthreads();
    if (tid == 0) {
        float mx = ls[0];
#pragma unroll
        for (int e = 1; e < NE; e++) mx = fmaxf(mx, ls[e]);
        float ex[NE], s = 0.0f;
#pragma unroll
        for (int e = 0; e < NE; e++) { ex[e] = expf(ls[e] - mx); s += ex[e]; }
        const float inv = 1.0f / s;
#pragma unroll
        for (int e = 0; e < NE; e++) g_coef[(size_t)token * NE + e] = ex[e] * inv;
    }
}

// ---------------------------------------------------------------------------
// Split z,c (fp32) -> bf16 hi/lo into both ping-pong A buffers, cols 0..511
// ---------------------------------------------------------------------------
__global__ void split_zc(const float* __restrict__ z, const float* __restrict__ c)
{
    const int g = blockIdx.x * 256 + threadIdx.x;   // one per 8 elems
    // total groups: NB*NT * (512/8) = 1,048,576
    const int cg = g & 63;
    const int bt = g >> 6;
    const float* src = (cg < 8) ? (z + (size_t)bt * 64 + cg * 8)
                                : (c + (size_t)bt * 448 + (cg - 8) * 8);
    float v[8];
    const float4 v0 = *(const float4*)src;
    const float4 v1 = *(const float4*)(src + 4);
    v[0]=v0.x; v[1]=v0.y; v[2]=v0.z; v[3]=v0.w;
    v[4]=v1.x; v[5]=v1.y; v[6]=v1.z; v[7]=v1.w;
    uint4 hv, lv; split8(v, hv, lv);
    const size_t d = (size_t)bt * KMAX + cg * 8;
    *(uint4*)(g_A0hi + d) = hv; *(uint4*)(g_A1hi + d) = hv;
    *(uint4*)(g_A0lo + d) = lv; *(uint4*)(g_A1lo + d) = lv;
}

// ---------------------------------------------------------------------------
// Mix+transpose+split weights: whi/wlo[b][n][k] = split( sum_e coef0[b,e] w[e][k][n] )
// ---------------------------------------------------------------------------
__global__ __launch_bounds__(256)
void mix_kernel(const float* __restrict__ w, int fin, int fout)
{
    __shared__ float c0[NB * NE];
    const int tid = threadIdx.x;
    c0[tid] = g_coef[(size_t)(tid >> 3) * NT * NE + (tid & 7)];
    __syncthreads();

    const int n  = blockIdx.x * 32 + (tid & 31);
    const int kb = blockIdx.y * 64 + (tid >> 5) * 8;

    float wr[NE][8];
#pragma unroll
    for (int e = 0; e < NE; e++)
#pragma unroll
        for (int kk = 0; kk < 8; kk++)
            wr[e][kk] = w[((size_t)e * fin + kb + kk) * fout + n];

    const size_t base = (size_t)n * fin + kb;
    const size_t plane = (size_t)fin * fout;
    for (int b = 0; b < NB; b++) {
        float m[8];
#pragma unroll
        for (int kk = 0; kk < 8; kk++) {
            float a = 0.0f;
#pragma unroll
            for (int e = 0; e < NE; e++) a = fmaf(c0[b * NE + e], wr[e][kk], a);
            m[kk] = a;
        }
        uint4 hv, lv; split8(m, hv, lv);
        const size_t off = (size_t)b * plane + base;
        *(uint4*)(g_whi + off) = hv;
        *(uint4*)(g_wlo + off) = lv;
    }
}

// ---------------------------------------------------------------------------
// Batched GEMM via ldmatrix + mma.sync (bf16, 3-pass split), BK=64, SW128.
// 256 threads = 8 warps (4 m-rows x 2 n-cols), warp tile 32m x 64n.
// Double-buffered cp.async. Epilogue: stage->biasmix->leaky->split/store.
// ---------------------------------------------------------------------------
#define STAGE_BYTES 65536          // Ahi 16K | Alo 16K | Bhi 16K | Blo 16K
#define SMEM_GEMM  (2 * STAGE_BYTES)

__global__ void __launch_bounds__(256, 1)
gemm_mma(const float* __restrict__ bias, float* __restrict__ dout,
         int aSel, int outSel, int fin, int fout, int doAct)
{
    extern __shared__ char smem[];
    const uint32_t sbase = smem_to_u32(smem);
    const int tid = threadIdx.x, w = tid >> 5, lane = tid & 31;
    const int b = blockIdx.z, m0 = blockIdx.y * 128, n0 = blockIdx.x * 128;

    const __nv_bfloat16* aHi = (aSel ? g_A1hi : g_A0hi) + (size_t)(b * NT + m0) * KMAX;
    const __nv_bfloat16* aLo = (aSel ? g_A1lo : g_A0lo) + (size_t)(b * NT + m0) * KMAX;
    const __nv_bfloat16* bHi = g_whi + ((size_t)b * fout + n0) * fin;
    const __nv_bfloat16* bLo = g_wlo + ((size_t)b * fout + n0) * fin;

    const int nChunks = fin >> 6;

    // ---- async tile loader: 128 rows x 64 k bf16, SW128, 4 tensors --------
    const int lrow = tid >> 1;                 // used twice (j-loop of 4)
    auto loadChunk = [&](int cidx) {
        const uint32_t st = sbase + (uint32_t)(cidx & 1) * STAGE_BYTES;
        const int k0 = cidx * 64;
#pragma unroll
        for (int j = 0; j < 4; j++) {
            const int idx = tid + j * 256;     // 0..1023
            const int row = idx >> 3;          // 0..127
            const int seg = idx & 7;           // 16B segment
            const uint32_t dsw = SWZ128((uint32_t)(row * 128 + seg * 16));
            const size_t ka = (size_t)row * KMAX + k0 + seg * 8;
            const size_t kb = (size_t)row * fin  + k0 + seg * 8;
            cp16(st +          dsw, aHi + ka);
            cp16(st + 16384u + dsw, aLo + ka);
            cp16(st + 32768u + dsw, bHi + kb);
            cp16(st + 49152u + dsw, bLo + kb);
        }
        cp_commit();
    };
    (void)lrow;

    float acc[2][8][4];
#pragma unroll
    for (int i = 0; i < 2; i++)
#pragma unroll
        for (int j = 0; j < 8; j++)
#pragma unroll
            for (int q = 0; q < 4; q++) acc[i][j][q] = 0.0f;

    const int wm0 = (w & 3) * 32;
    const int wn0 = (w >> 2) * 64;
    // ldmatrix lane address components
    const int la_r = lane & 15;                // A row within m16
    const int la_c = (lane >> 4) * 8;          // A k half
    const int lb_row = (((lane >> 3) >> 1) << 3) + (lane & 7);   // B n row off
    const int lb_k   = ((lane >> 3) & 1) * 8;                    // B k half

    loadChunk(0);

    for (int cidx = 0; cidx < nChunks; cidx++) {
        if (cidx + 1 < nChunks) {
            loadChunk(cidx + 1);
            asm volatile("cp.async.wait_group 1;" ::: "memory");
        } else {
            asm volatile("cp.async.wait_group 0;" ::: "memory");
        }
        __syncthreads();

        const uint32_t st = sbase + (uint32_t)(cidx & 1) * STAGE_BYTES;
#pragma unroll
        for (int ks = 0; ks < 4; ks++) {
            const int ko = ks * 16;
            uint32_t ahi[2][4], alo[2][4];
#pragma unroll
            for (int mi = 0; mi < 2; mi++) {
                const uint32_t ao = SWZ128((uint32_t)((wm0 + mi * 16 + la_r) * 128
                                                      + (ko + la_c) * 2));
                ldsm4(ahi[mi], st + ao);
                ldsm4(alo[mi], st + 16384u + ao);
            }
            uint32_t bh[8][2], bl[8][2];
#pragma unroll
            for (int p = 0; p < 4; p++) {
                const uint32_t bo = SWZ128((uint32_t)((wn0 + p * 16 + lb_row) * 128
                                                      + (ko + lb_k) * 2));
                uint32_t r4[4];
                ldsm4(r4, st + 32768u + bo);
                bh[2*p][0] = r4[0]; bh[2*p][1] = r4[1];
                bh[2*p+1][0] = r4[2]; bh[2*p+1][1] = r4[3];
                ldsm4(r4, st + 49152u + bo);
                bl[2*p][0] = r4[0]; bl[2*p][1] = r4[1];
                bl[2*p+1][0] = r4[2]; bl[2*p+1][1] = r4[3];
            }
#pragma unroll
            for (int mi = 0; mi < 2; mi++)
#pragma unroll
                for (int nf = 0; nf < 8; nf++) {
                    mma16816(acc[mi][nf], ahi[mi], bh[nf]);
                    mma16816(acc[mi][nf], ahi[mi], bl[nf]);
                    mma16816(acc[mi][nf], alo[mi], bh[nf]);
                }
        }
        __syncthreads();
    }

    // ---------------- epilogue ----------------
    float* stage  = (float*)smem;                       // [128][130]
    float* bias_s = (float*)(smem + 66560);             // [8][128]
    float* coef_s = (float*)(smem + 66560 + 4096);      // [128][8]
#pragma unroll
    for (int j = 0; j < 4; j++) {
        const int idx = tid + j * 256;                  // 0..1023
        bias_s[idx] = bias[(size_t)(idx >> 7) * fout + n0 + (idx & 127)];
        coef_s[idx] = g_coef[((size_t)b * NT + m0) * NE + idx];
    }
    // phase 1: dump accumulators
    {
        const int g = lane >> 2, tig = lane & 3;
#pragma unroll
        for (int mi = 0; mi < 2; mi++)
#pragma unroll
            for (int nf = 0; nf < 8; nf++) {
                const int r0 = wm0 + mi * 16 + g;
                const int cb = wn0 + nf * 8 + tig * 2;
                *(float2*)&stage[r0 * 130 + cb] =
                    make_float2(acc[mi][nf][0], acc[mi][nf][1]);
                *(float2*)&stage[(r0 + 8) * 130 + cb] =
                    make_float2(acc[mi][nf][2], acc[mi][nf][3]);
            }
    }
    __syncthreads();

    // phase 2: bias-mix + activation + store
    __nv_bfloat16* oHi = (outSel == 0) ? g_A1hi : g_A0hi;
    __nv_bfloat16* oLo = (outSel == 0) ? g_A1lo : g_A0lo;
#pragma unroll
    for (int it = 0; it < 8; it++) {
        const int idx = tid + it * 256;                 // 0..2047
        const int r = idx >> 4, cg = idx & 15;
        const float* cf = &coef_s[r * 8];
        float v[8];
#pragma unroll
        for (int jj = 0; jj < 8; jj++) {
            const int cc = cg * 8 + jj;
            float bm = 0.0f;
#pragma unroll
            for (int e = 0; e < NE; e++) bm = fmaf(cf[e], bias_s[e * 128 + cc], bm);
            float x = stage[r * 130 + cc] + bm;
            v[jj] = doAct ? LRELU(x) : x;
        }
        if (outSel == 2) {
            float* orow = dout + ((size_t)(b * NT + m0 + r)) * fout + n0 + cg * 8;
            *(float4*)orow       = make_float4(v[0], v[1], v[2], v[3]);
            *(float4*)(orow + 4) = make_float4(v[4], v[5], v[6], v[7]);
        } else {
            uint4 hv, lv; split8(v, hv, lv);
            const size_t d = ((size_t)(b * NT + m0 + r)) * KMAX + 512 + n0 + cg * 8;
            *(uint4*)(oHi + d) = hv;
            *(uint4*)(oLo + d) = lv;
        }
    }
}

// ---------------------------------------------------------------------------
extern "C" void kernel_launch(void* const* d_in, const int* in_sizes, int n_in,
                              void* d_out, int out_size)
{
    (void)in_sizes; (void)n_in; (void)out_size;
    const float* z  = (const float*)d_in[0];
    const float* c  = (const float*)d_in[1];
    const float* w[5]  = { (const float*)d_in[2], (const float*)d_in[4],
                           (const float*)d_in[6], (const float*)d_in[8],
                           (const float*)d_in[10] };
    const float* bs[5] = { (const float*)d_in[3], (const float*)d_in[5],
                           (const float*)d_in[7], (const float*)d_in[9],
                           (const float*)d_in[11] };
    const float* gw0 = (const float*)d_in[12];
    const float* gb0 = (const float*)d_in[13];
    const float* gw1 = (const float*)d_in[14];
    const float* gb1 = (const float*)d_in[15];
    const float* gw2 = (const float*)d_in[16];
    const float* gb2 = (const float*)d_in[17];
    float* out = (float*)d_out;

    cudaFuncSetAttribute(gemm_mma, cudaFuncAttributeMaxDynamicSharedMemorySize, SMEM_GEMM);

    gate_kernel<<<NB * NT, 64>>>(z, c, gw0, gb0, gw1, gb1, gw2, gb2);
    split_zc<<<4096, 256>>>(z, c);

    static const int fins[5]   = { 512, 1536, 1536, 1536, 1536 };
    static const int fouts[5]  = { 1024, 1024, 1024, 1024, 512 };
    static const int aSel[5]   = { 0, 1, 0, 1, 0 };
    static const int outSel[5] = { 0, 1, 0, 1, 2 };

    for (int L = 0; L < 5; L++) {
        dim3 mgrid(fouts[L] / 32, fins[L] / 64);
        mix_kernel<<<mgrid, 256>>>(w[L], fins[L], fouts[L]);
        dim3 ggrid(fouts[L] / 128, NT / 128, NB);
        gemm_mma<<<ggrid, 256, SMEM_GEMM>>>(bs[L], out, aSel[L], outSel[L],
                                            fins[L], fouts[L], (L < 4) ? 1 : 0);
    }
}